// round 15
// baseline (speedup 1.0000x reference)
#include <cuda_runtime.h>
#include <cuda_fp16.h>
#include <cstdint>

// Problem constants
#define Bn   64
#define Tn   2048
#define Fn   128
#define Hn   512
#define HSn  32           // hidden groups (CTAs per batch group)
#define BSn  4            // batch groups
#define BCn  16           // batches per CTA
#define NT   256          // 8 warps (proven topology)

// hx smem: 40 k16-groups x 136 u32 (128 used: n*8 + pos, 8 pad)
#define HXG      136
#define HX_U32   (40*HXG)              // 5440
#define GP_RS    18                    // gpart row stride (floats, even -> aligned float2)
#define GP_PER_W (64*GP_RS)            // 1152
#define GP_FLOATS (8*GP_PER_W)         // 9216
#define SM_HX   0
#define SM_GP   (SM_HX + HX_U32)
#define SM_BIAS (SM_GP + GP_FLOATS)
#define SM_TOTAL (SM_BIAS + 64)        // 14720 words = 58880 B

#define FLG_STR 8
#define SENT 0x7FFF7FFFu               // (NaN|NaN) half2 — impossible as packed h data

// Scratch (no cudaMalloc allowed)
__device__ float    g_hf[Bn * Hn];                 // fp32 final h (for output GEMV)
__device__ unsigned g_hx[BSn][4][HSn * 128];       // packed half2 h exchange, 4-deep rotation
__device__ unsigned g_xp[BSn][Tn][8 * 128];        // pre-packed x in B-fragment layout (32MB)
__device__ unsigned g_flag[BSn * HSn * FLG_STR];   // final-output gate only

__device__ __forceinline__ unsigned h2bits(float a, float b) {
    __half2 h = __floats2half2_rn(a, b);
    return *reinterpret_cast<unsigned*>(&h);
}

__device__ __forceinline__ void mma_f16(float* c,
                                        unsigned a0, unsigned a1, unsigned a2, unsigned a3,
                                        unsigned b0, unsigned b1) {
    asm volatile(
        "mma.sync.aligned.m16n8k16.row.col.f32.f16.f16.f32 "
        "{%0,%1,%2,%3}, {%4,%5,%6,%7}, {%8,%9}, {%0,%1,%2,%3};"
        : "+f"(c[0]), "+f"(c[1]), "+f"(c[2]), "+f"(c[3])
        : "r"(a0), "r"(a1), "r"(a2), "r"(a3), "r"(b0), "r"(b1));
}

__device__ __forceinline__ float tanh_ap(float x) {
    float y;
    asm("tanh.approx.f32 %0, %1;" : "=f"(y) : "f"(x));
    return y;
}
__device__ __forceinline__ float sigmoid_ap(float x) {
    return fmaf(tanh_ap(0.5f * x), 0.5f, 0.5f);
}

// Re-run every graph replay: zero flags, sentinel-fill ALL g_hx buffers.
__global__ void init_state_kernel() {
    int i = blockIdx.x * blockDim.x + threadIdx.x;
    if (i < BSn * HSn * FLG_STR) g_flag[i] = 0u;
    unsigned* hx = &g_hx[0][0][0];
    for (int j = i; j < BSn * 4 * HSn * 128; j += gridDim.x * blockDim.x)
        hx[j] = SENT;
}

// Pre-pack x[b,t,f] -> g_xp[bg][t][g*128 + n*8 + pos] (half2, hx B-fragment layout)
__global__ void prepack_x_kernel(const float* __restrict__ x) {
    int bg = blockIdx.x >> 11;
    int t  = blockIdx.x & 2047;
    unsigned* dst = g_xp[bg][t];
    for (int j = threadIdx.x; j < 1024; j += blockDim.x) {
        int g   = j >> 7;                          // hx group 32+g
        int idx = j & 127;
        int n   = idx >> 3;
        int pos = idx & 7;
        int p   = (pos >> 1) | ((pos & 1) << 2);   // inverse of pos = ((p&3)<<1)|(p>>2)
        int f   = (g * 8 + p) * 2;
        const float* xb = x + ((size_t)(bg * BCn + n) * Tn + t) * Fn + f;
        float2 v = *reinterpret_cast<const float2*>(xb);
        dst[j] = h2bits(v.x, v.y);
    }
}

__global__ void __launch_bounds__(NT, 1) lstm_persist(
    const float* __restrict__ Wih,  const float* __restrict__ Whh,
    const float* __restrict__ bih,  const float* __restrict__ bhh,
    const float* __restrict__ Wout, const float* __restrict__ bout,
    float* __restrict__ out)
{
    extern __shared__ float sm[];
    unsigned* hxs = reinterpret_cast<unsigned*>(sm + SM_HX);
    float* gpart  = sm + SM_GP;
    float* bsm    = sm + SM_BIAS;

    const int tid = threadIdx.x;
    const int l   = tid & 31;
    const int w   = tid >> 5;             // warp 0..7 => GEMM k-slice groups 5w..5w+4
    const int q   = blockIdx.x & 31;      // hidden group (16 units)
    const int bg  = blockIdx.x >> 5;      // batch group
    const int b0  = bg * BCn;
    unsigned* flg = g_flag + bg * HSn * FLG_STR;

    // ---- one-time: A fragments (fp16) -> registers ----
    unsigned Ar[5][4][4];
    {
        const int r0 = l >> 2;
        const int c0 = 2 * (l & 3);
        #pragma unroll
        for (int s = 0; s < 5; ++s)
            #pragma unroll
            for (int g = 0; g < 4; ++g)
                #pragma unroll
                for (int j = 0; j < 4; ++j) {
                    int row = r0 + ((j & 1) << 3);
                    int col = c0 + ((j >> 1) << 3);
                    int grow = g * Hn + q * 16 + row;
                    int k    = w * 80 + s * 16 + col;    // k,k+1 same side of 512
                    float v0, v1;
                    if (k < Hn) {
                        v0 = Whh[(size_t)grow * Hn + k];
                        v1 = Whh[(size_t)grow * Hn + k + 1];
                    } else {
                        v0 = Wih[(size_t)grow * Fn + (k - Hn)];
                        v1 = Wih[(size_t)grow * Fn + (k - Hn) + 1];
                    }
                    Ar[s][g][j] = h2bits(v0, v1);
                }
    }
    if (tid < 64) {
        int e = tid >> 4, r = tid & 15;
        int grow = e * Hn + q * 16 + r;
        bsm[tid] = bih[grow] + bhh[grow];
    }
    // zero hx (h0 = 0), then copy x(0) from prepacked g_xp (warp w -> group 32+w)
    for (int i = tid; i < HX_U32; i += NT) hxs[i] = 0u;
    __syncthreads();
    {
        const unsigned* xsrc = g_xp[bg][0];
        uint4 v = __ldcg(reinterpret_cast<const uint4*>(xsrc + w * 128) + l);
        *reinterpret_cast<uint4*>(hxs + (32 + w) * HXG + 4 * l) = v;
    }

    float creg = 0.f;                      // cell state: thread owns (bb, ju)
    const int bb = tid >> 4, ju = tid & 15;
    const int n0_   = l >> 2;
    const int boff0 = n0_ * 8 + 2 * (l & 3);
    const int boff1 = (n0_ + 8) * 8 + 2 * (l & 3);

    for (int t = 0; t < Tn; ++t) {
        __syncthreads();   // hx(t) ready

        // ---- GEMM: warp computes 64x16 partial over its K=80 slice (fp16) ----
        float acc[4][2][4];
        #pragma unroll
        for (int g = 0; g < 4; ++g)
            #pragma unroll
            for (int h2 = 0; h2 < 2; ++h2)
                #pragma unroll
                for (int j = 0; j < 4; ++j) acc[g][h2][j] = 0.f;

        #pragma unroll
        for (int s = 0; s < 5; ++s) {
            const unsigned* gb = hxs + (5 * w + s) * HXG;
            uint2 v0 = *reinterpret_cast<const uint2*>(gb + boff0);
            uint2 v1 = *reinterpret_cast<const uint2*>(gb + boff1);
            #pragma unroll
            for (int g = 0; g < 4; ++g) {
                mma_f16(acc[g][0], Ar[s][g][0], Ar[s][g][1], Ar[s][g][2], Ar[s][g][3], v0.x, v0.y);
                mma_f16(acc[g][1], Ar[s][g][0], Ar[s][g][1], Ar[s][g][2], Ar[s][g][3], v1.x, v1.y);
            }
        }

        // ---- write per-warp partials ----
        {
            int r0 = l >> 2, cc0 = 2 * (l & 3);
            float* gp = gpart + w * GP_PER_W;
            #pragma unroll
            for (int g = 0; g < 4; ++g)
                #pragma unroll
                for (int h2 = 0; h2 < 2; ++h2) {
                    *reinterpret_cast<float2*>(gp + (g * 16 + r0) * GP_RS + h2 * 8 + cc0) =
                        make_float2(acc[g][h2][0], acc[g][h2][1]);
                    *reinterpret_cast<float2*>(gp + (g * 16 + r0 + 8) * GP_RS + h2 * 8 + cc0) =
                        make_float2(acc[g][h2][2], acc[g][h2][3]);
                }
        }
        __syncthreads();   // S1: partials ready

        // ---- reduce 8 partials (tree) + bias, LSTM cell ----
        float gate[4];
        #pragma unroll
        for (int g = 0; g < 4; ++g) {
            int row = g * 16 + ju;
            const float* gpr = gpart + row * GP_RS + bb;
            float p0 = gpr[0 * GP_PER_W];
            float p1 = gpr[1 * GP_PER_W];
            float p2 = gpr[2 * GP_PER_W];
            float p3 = gpr[3 * GP_PER_W];
            float p4 = gpr[4 * GP_PER_W];
            float p5 = gpr[5 * GP_PER_W];
            float p6 = gpr[6 * GP_PER_W];
            float p7 = gpr[7 * GP_PER_W];
            gate[g] = bsm[row] + (((p0 + p1) + (p2 + p3)) + ((p4 + p5) + (p6 + p7)));
        }
        float iv = sigmoid_ap(gate[0]);
        float fv = sigmoid_ap(gate[1]);
        float gv = tanh_ap(gate[2]);
        float ov = sigmoid_ap(gate[3]);
        creg = fv * creg + iv * gv;
        float hv = ov * tanh_ap(creg);

        // fence: acquire side for prior poll loop, release side for the h stores below
        asm volatile("fence.acq_rel.gpu;" ::: "memory");

        // ---- pack h pair -> local smem (own group) + gmem exchange + buffer reset ----
        float hv_hi = __shfl_down_sync(0xffffffffu, hv, 1);
        if (t + 1 < Tn) {
            if (!(ju & 1)) {
                int jp = ju >> 1;
                int pos = ((jp & 3) << 1) | (jp >> 2);
                unsigned pk = h2bits(hv, hv_hi);
                int off = q * 128 + bb * 8 + pos;
                hxs[q * HXG + bb * 8 + pos] = pk;            // own group local (no gmem trip)
                unsigned* dst = &g_hx[bg][(t + 1) & 3][off];
                asm volatile("st.global.cg.u32 [%0], %1;" :: "l"(dst), "r"(pk) : "memory");
                // reset buffer consumed 2 steps ago (next written at t+2); safe per skew bound
                unsigned* rst = &g_hx[bg][(t + 3) & 3][off];
                asm volatile("st.global.cg.u32 [%0], %1;" :: "l"(rst), "r"(SENT) : "memory");
            }
        } else {
            g_hf[(size_t)(b0 + bb) * Hn + q * 16 + ju] = hv; // final h fp32
        }
        __syncthreads();   // S2: own-q smem store ordered vs next-iter GEMM reads

        if (t + 1 < Tn) {
            // ---- x group copy first (always valid; latency overlaps the h polls) ----
            {
                const unsigned* xsrc = g_xp[bg][t + 1];
                uint4 v = __ldcg(reinterpret_cast<const uint4*>(xsrc + w * 128) + l);
                *reinterpret_cast<uint4*>(hxs + (32 + w) * HXG + 4 * l) = v;
            }
            // ---- fused poll+copy: sentinel retry on this warp's 4 h groups ----
            const unsigned* src = g_hx[bg][(t + 1) & 3];
            bool done0 = (4 * w + 0 == q);
            bool done1 = (4 * w + 1 == q);
            bool done2 = (4 * w + 2 == q);
            bool done3 = (4 * w + 3 == q);
            for (;;) {
                bool all = true;
                #pragma unroll
                for (int s = 0; s < 4; ++s) {
                    bool& dn = (s == 0) ? done0 : (s == 1) ? done1 : (s == 2) ? done2 : done3;
                    if (!dn) {
                        int gg = 4 * w + s;
                        uint4 v;
                        asm volatile("ld.global.cg.v4.u32 {%0,%1,%2,%3}, [%4];"
                                     : "=r"(v.x), "=r"(v.y), "=r"(v.z), "=r"(v.w)
                                     : "l"(src + gg * 128 + 4 * l) : "memory");
                        if (v.x != SENT && v.y != SENT && v.z != SENT && v.w != SENT) {
                            *reinterpret_cast<uint4*>(hxs + gg * HXG + 4 * l) = v;
                            dn = true;
                        } else {
                            all = false;
                        }
                    }
                }
                if (__all_sync(0xffffffffu, all)) break;
                __nanosleep(20);
            }
        }
    }

    // ---- final gate: flags only here (g_hf visibility for the output GEMV) ----
    __syncthreads();
    if (tid == 0) {
        asm volatile("st.release.gpu.global.u32 [%0], %1;"
                     :: "l"(flg + q * FLG_STR), "r"(1u) : "memory");
    }

    // ---- final: out[b, o] = relu(h_T) . Wout[o] + bout[o] (layer 1 is dead code) ----
    if (q == 0) {
        if (tid < HSn) {
            for (;;) {
                unsigned vv;
                asm volatile("ld.acquire.gpu.global.u32 %0, [%1];"
                             : "=r"(vv) : "l"(flg + tid * FLG_STR) : "memory");
                if (vv >= 1u) break;
                __nanosleep(64);
            }
        }
        __syncthreads();
        if (tid < BCn * 4) {
            int b = tid >> 2, o = tid & 3;
            const float* hb = g_hf + (size_t)(b0 + b) * Hn;
            const float* wo = Wout + (size_t)o * Hn;
            float sum = bout[o];
            #pragma unroll 8
            for (int j = 0; j < Hn; j += 4) {
                float4 hv = __ldcg(reinterpret_cast<const float4*>(hb + j));
                float4 wv = *reinterpret_cast<const float4*>(wo + j);
                sum += fmaxf(hv.x, 0.f) * wv.x + fmaxf(hv.y, 0.f) * wv.y
                     + fmaxf(hv.z, 0.f) * wv.z + fmaxf(hv.w, 0.f) * wv.w;
            }
            out[(b0 + b) * 4 + o] = sum;
        }
    }
}

extern "C" void kernel_launch(void* const* d_in, const int* in_sizes, int n_in,
                              void* d_out, int out_size) {
    const float* x    = (const float*)d_in[0];
    const float* Wih  = (const float*)d_in[1];
    const float* Whh  = (const float*)d_in[2];
    const float* bih  = (const float*)d_in[3];
    const float* bhh  = (const float*)d_in[4];
    // d_in[5..8]: layer-1 weights — provably unused by the reference output
    const float* Wout = (const float*)d_in[9];
    const float* bout = (const float*)d_in[10];
    float* out = (float*)d_out;

    cudaFuncSetAttribute(lstm_persist, cudaFuncAttributeMaxDynamicSharedMemorySize,
                         SM_TOTAL * (int)sizeof(float));
    init_state_kernel<<<64, 1024>>>();
    prepack_x_kernel<<<BSn * Tn, 256>>>(x);
    lstm_persist<<<HSn * BSn, NT, SM_TOTAL * (int)sizeof(float)>>>(
        Wih, Whh, bih, bhh, Wout, bout, out);
}

// round 16
// speedup vs baseline: 1.2929x; 1.2929x over previous
#include <cuda_runtime.h>
#include <cuda_fp16.h>
#include <cstdint>

// Problem constants
#define Bn   64
#define Tn   2048
#define Fn   128
#define Hn   512
#define HSn  32           // hidden groups (CTAs per batch group)
#define BSn  4            // batch groups
#define BCn  16           // batches per CTA
#define NT   256          // 8 warps (proven R14 topology)

// hx smem: 40 k16-groups x 136 u32 (128 used: n*8 + pos, 8 pad)
#define HXG      136
#define HX_U32   (40*HXG)              // 5440
#define GP_RS    18                    // gpart row stride (floats, even -> aligned float2)
#define GP_PER_W (64*GP_RS)            // 1152
#define GP_FLOATS (8*GP_PER_W)         // 9216
#define SM_HX   0
#define SM_GP   (SM_HX + HX_U32)
#define SM_BIAS (SM_GP + GP_FLOATS)
#define SM_TOTAL (SM_BIAS + 64)        // 14720 words = 58880 B

#define FLG_STR 32                     // one 128B L2 line per flag (no false sharing)

// Scratch (no cudaMalloc allowed)
__device__ float    g_hf[Bn * Hn];                 // fp32 final h (for output GEMV)
__device__ unsigned g_hx[BSn][2][HSn * 128];       // packed half2 h exchange, dbl-buffered
__device__ unsigned g_xp[BSn][Tn][8 * 128];        // pre-packed x in B-fragment layout (32MB)
__device__ unsigned g_flag[BSn * HSn * FLG_STR];   // counting flags: 8 arrivals per step

__device__ __forceinline__ unsigned h2bits(float a, float b) {
    __half2 h = __floats2half2_rn(a, b);
    return *reinterpret_cast<unsigned*>(&h);
}

__device__ __forceinline__ void mma_f16(float* c,
                                        unsigned a0, unsigned a1, unsigned a2, unsigned a3,
                                        unsigned b0, unsigned b1) {
    asm volatile(
        "mma.sync.aligned.m16n8k16.row.col.f32.f16.f16.f32 "
        "{%0,%1,%2,%3}, {%4,%5,%6,%7}, {%8,%9}, {%0,%1,%2,%3};"
        : "+f"(c[0]), "+f"(c[1]), "+f"(c[2]), "+f"(c[3])
        : "r"(a0), "r"(a1), "r"(a2), "r"(a3), "r"(b0), "r"(b1));
}

__device__ __forceinline__ float tanh_ap(float x) {
    float y;
    asm("tanh.approx.f32 %0, %1;" : "=f"(y) : "f"(x));
    return y;
}
__device__ __forceinline__ float sigmoid_ap(float x) {
    return fmaf(tanh_ap(0.5f * x), 0.5f, 0.5f);
}

__global__ void init_flags_kernel() {
    int i = blockIdx.x * blockDim.x + threadIdx.x;
    if (i < BSn * HSn * FLG_STR) g_flag[i] = 0u;
}

// Pre-pack x[b,t,f] -> g_xp[bg][t][g*128 + n*8 + pos] (half2, hx B-fragment layout)
__global__ void prepack_x_kernel(const float* __restrict__ x) {
    int bg = blockIdx.x >> 11;
    int t  = blockIdx.x & 2047;
    unsigned* dst = g_xp[bg][t];
    for (int j = threadIdx.x; j < 1024; j += blockDim.x) {
        int g   = j >> 7;                          // hx group 32+g
        int idx = j & 127;
        int n   = idx >> 3;
        int pos = idx & 7;
        int p   = (pos >> 1) | ((pos & 1) << 2);   // inverse of pos = ((p&3)<<1)|(p>>2)
        int f   = (g * 8 + p) * 2;
        const float* xb = x + ((size_t)(bg * BCn + n) * Tn + t) * Fn + f;
        float2 v = *reinterpret_cast<const float2*>(xb);
        dst[j] = h2bits(v.x, v.y);
    }
}

__global__ void __launch_bounds__(NT, 1) lstm_persist(
    const float* __restrict__ Wih,  const float* __restrict__ Whh,
    const float* __restrict__ bih,  const float* __restrict__ bhh,
    const float* __restrict__ Wout, const float* __restrict__ bout,
    float* __restrict__ out)
{
    extern __shared__ float sm[];
    unsigned* hxs = reinterpret_cast<unsigned*>(sm + SM_HX);
    float* gpart  = sm + SM_GP;
    float* bsm    = sm + SM_BIAS;

    const int tid = threadIdx.x;
    const int l   = tid & 31;
    const int w   = tid >> 5;             // warp 0..7 => GEMM k-slice groups 5w..5w+4
    const int q   = blockIdx.x & 31;      // hidden group (16 units)
    const int bg  = blockIdx.x >> 5;      // batch group
    const int b0  = bg * BCn;
    unsigned* flg = g_flag + bg * HSn * FLG_STR;

    // ---- one-time: A fragments (fp16) -> registers ----
    unsigned Ar[5][4][4];
    {
        const int r0 = l >> 2;
        const int c0 = 2 * (l & 3);
        #pragma unroll
        for (int s = 0; s < 5; ++s)
            #pragma unroll
            for (int g = 0; g < 4; ++g)
                #pragma unroll
                for (int j = 0; j < 4; ++j) {
                    int row = r0 + ((j & 1) << 3);
                    int col = c0 + ((j >> 1) << 3);
                    int grow = g * Hn + q * 16 + row;
                    int k    = w * 80 + s * 16 + col;    // k,k+1 same side of 512
                    float v0, v1;
                    if (k < Hn) {
                        v0 = Whh[(size_t)grow * Hn + k];
                        v1 = Whh[(size_t)grow * Hn + k + 1];
                    } else {
                        v0 = Wih[(size_t)grow * Fn + (k - Hn)];
                        v1 = Wih[(size_t)grow * Fn + (k - Hn) + 1];
                    }
                    Ar[s][g][j] = h2bits(v0, v1);
                }
    }
    if (tid < 64) {
        int e = tid >> 4, r = tid & 15;
        int grow = e * Hn + q * 16 + r;
        bsm[tid] = bih[grow] + bhh[grow];
    }
    // zero hx (h0 = 0), then copy x(0) from prepacked g_xp (warp w -> group 32+w)
    for (int i = tid; i < HX_U32; i += NT) hxs[i] = 0u;
    __syncthreads();
    {
        const unsigned* xsrc = g_xp[bg][0];
        uint4 v = __ldcg(reinterpret_cast<const uint4*>(xsrc + w * 128) + l);
        *reinterpret_cast<uint4*>(hxs + (32 + w) * HXG + 4 * l) = v;
    }

    float creg = 0.f;                      // cell state: thread owns (bb, ju)
    const int bb = tid >> 4, ju = tid & 15;
    const int n0_   = l >> 2;
    const int boff0 = n0_ * 8 + 2 * (l & 3);
    const int boff1 = (n0_ + 8) * 8 + 2 * (l & 3);

    for (int t = 0; t < Tn; ++t) {
        __syncthreads();   // hx(t) ready

        // ---- GEMM: warp computes 64x16 partial over its K=80 slice (fp16) ----
        float acc[4][2][4];
        #pragma unroll
        for (int g = 0; g < 4; ++g)
            #pragma unroll
            for (int h2 = 0; h2 < 2; ++h2)
                #pragma unroll
                for (int j = 0; j < 4; ++j) acc[g][h2][j] = 0.f;

        #pragma unroll
        for (int s = 0; s < 5; ++s) {
            const unsigned* gb = hxs + (5 * w + s) * HXG;
            uint2 v0 = *reinterpret_cast<const uint2*>(gb + boff0);
            uint2 v1 = *reinterpret_cast<const uint2*>(gb + boff1);
            #pragma unroll
            for (int g = 0; g < 4; ++g) {
                mma_f16(acc[g][0], Ar[s][g][0], Ar[s][g][1], Ar[s][g][2], Ar[s][g][3], v0.x, v0.y);
                mma_f16(acc[g][1], Ar[s][g][0], Ar[s][g][1], Ar[s][g][2], Ar[s][g][3], v1.x, v1.y);
            }
        }

        // ---- write per-warp partials ----
        {
            int r0 = l >> 2, cc0 = 2 * (l & 3);
            float* gp = gpart + w * GP_PER_W;
            #pragma unroll
            for (int g = 0; g < 4; ++g)
                #pragma unroll
                for (int h2 = 0; h2 < 2; ++h2) {
                    *reinterpret_cast<float2*>(gp + (g * 16 + r0) * GP_RS + h2 * 8 + cc0) =
                        make_float2(acc[g][h2][0], acc[g][h2][1]);
                    *reinterpret_cast<float2*>(gp + (g * 16 + r0 + 8) * GP_RS + h2 * 8 + cc0) =
                        make_float2(acc[g][h2][2], acc[g][h2][3]);
                }
        }
        __syncthreads();   // S1: partials ready

        // ---- reduce 8 partials (tree) + bias, LSTM cell ----
        float gate[4];
        #pragma unroll
        for (int g = 0; g < 4; ++g) {
            int row = g * 16 + ju;
            const float* gpr = gpart + row * GP_RS + bb;
            float p0 = gpr[0 * GP_PER_W];
            float p1 = gpr[1 * GP_PER_W];
            float p2 = gpr[2 * GP_PER_W];
            float p3 = gpr[3 * GP_PER_W];
            float p4 = gpr[4 * GP_PER_W];
            float p5 = gpr[5 * GP_PER_W];
            float p6 = gpr[6 * GP_PER_W];
            float p7 = gpr[7 * GP_PER_W];
            gate[g] = bsm[row] + (((p0 + p1) + (p2 + p3)) + ((p4 + p5) + (p6 + p7)));
        }
        float iv = sigmoid_ap(gate[0]);
        float fv = sigmoid_ap(gate[1]);
        float gv = tanh_ap(gate[2]);
        float ov = sigmoid_ap(gate[3]);
        creg = fv * creg + iv * gv;
        float hv = ov * tanh_ap(creg);

        // ---- pack h pair (ju even lanes) -> local smem (own group) + gmem exchange ----
        float hv_hi = __shfl_down_sync(0xffffffffu, hv, 1);
        if (t + 1 < Tn) {
            if (!(ju & 1)) {
                int jp = ju >> 1;
                int pos = ((jp & 3) << 1) | (jp >> 2);
                unsigned pk = h2bits(hv, hv_hi);
                hxs[q * HXG + bb * 8 + pos] = pk;            // own group local (no gmem trip)
                g_hx[bg][(t + 1) & 1][q * 128 + bb * 8 + pos] = pk;
            }
        } else {
            g_hf[(size_t)(b0 + bb) * Hn + q * 16 + ju] = hv; // final h fp32
        }
        // early per-warp release: count 8 arrivals per step on this group's flag
        __syncwarp();      // orders all lanes' g_hx/g_hf stores before lane0's release
        if (l == 0) {
            asm volatile("red.release.gpu.global.add.u32 [%0], %1;"
                         :: "l"(flg + q * FLG_STR), "r"(1u) : "memory");
        }
        __syncthreads();   // S2: own-q smem store ordered vs next-iter GEMM reads

        if (t + 1 < Tn) {
            // ---- x group copy FIRST (flag-independent; latency overlaps the poll) ----
            {
                const unsigned* xsrc = g_xp[bg][t + 1];
                uint4 v = __ldcg(reinterpret_cast<const uint4*>(xsrc + w * 128) + l);
                *reinterpret_cast<uint4*>(hxs + (32 + w) * HXG + 4 * l) = v;
            }
            // ---- per-warp poll: warp w needs producers 4w..4w+3 (count >= 8*(t+1)) ----
            const unsigned tgt = 8u * (unsigned)(t + 1);
            const int qq = 4 * w + (l & 3);
            bool need = (l < 4) && (qq != q);
            bool ok = !need;
            for (;;) {
                if (!ok) {
                    unsigned vv;
                    asm volatile("ld.acquire.gpu.global.u32 %0, [%1];"
                                 : "=r"(vv) : "l"(flg + qq * FLG_STR) : "memory");
                    ok = vv >= tgt;
                }
                if (__all_sync(0xffffffffu, ok)) break;
                __nanosleep(20);
            }
            // ---- copy this warp's 4 h groups (packed u32, uint4) ----
            const unsigned* src = g_hx[bg][(t + 1) & 1];
            #pragma unroll
            for (int s = 0; s < 4; ++s) {
                int gg = 4 * w + s;
                if (gg == q) continue;
                uint4 v = __ldcg(reinterpret_cast<const uint4*>(src + gg * 128) + l);
                *reinterpret_cast<uint4*>(hxs + gg * HXG + 4 * l) = v;
            }
        }
    }

    // ---- final: out[b, o] = relu(h_T) . Wout[o] + bout[o] (layer 1 is dead code) ----
    if (q == 0) {
        const unsigned tgt = 8u * (unsigned)Tn;
        if (tid < HSn) {
            for (;;) {
                unsigned vv;
                asm volatile("ld.acquire.gpu.global.u32 %0, [%1];"
                             : "=r"(vv) : "l"(flg + tid * FLG_STR) : "memory");
                if (vv >= tgt) break;
                __nanosleep(64);
            }
        }
        __syncthreads();
        if (tid < BCn * 4) {
            int b = tid >> 2, o = tid & 3;
            const float* hb = g_hf + (size_t)(b0 + b) * Hn;
            const float* wo = Wout + (size_t)o * Hn;
            float sum = bout[o];
            #pragma unroll 8
            for (int j = 0; j < Hn; j += 4) {
                float4 hv = __ldcg(reinterpret_cast<const float4*>(hb + j));
                float4 wv = *reinterpret_cast<const float4*>(wo + j);
                sum += fmaxf(hv.x, 0.f) * wv.x + fmaxf(hv.y, 0.f) * wv.y
                     + fmaxf(hv.z, 0.f) * wv.z + fmaxf(hv.w, 0.f) * wv.w;
            }
            out[(b0 + b) * 4 + o] = sum;
        }
    }
}

extern "C" void kernel_launch(void* const* d_in, const int* in_sizes, int n_in,
                              void* d_out, int out_size) {
    const float* x    = (const float*)d_in[0];
    const float* Wih  = (const float*)d_in[1];
    const float* Whh  = (const float*)d_in[2];
    const float* bih  = (const float*)d_in[3];
    const float* bhh  = (const float*)d_in[4];
    // d_in[5..8]: layer-1 weights — provably unused by the reference output
    const float* Wout = (const float*)d_in[9];
    const float* bout = (const float*)d_in[10];
    float* out = (float*)d_out;

    cudaFuncSetAttribute(lstm_persist, cudaFuncAttributeMaxDynamicSharedMemorySize,
                         SM_TOTAL * (int)sizeof(float));
    init_flags_kernel<<<8, 512>>>();
    prepack_x_kernel<<<BSn * Tn, 256>>>(x);
    lstm_persist<<<HSn * BSn, NT, SM_TOTAL * (int)sizeof(float)>>>(
        Wih, Whh, bih, bhh, Wout, bout, out);
}